// round 2
// baseline (speedup 1.0000x reference)
#include <cuda_runtime.h>

#define DE 128
#define BMAX 8192
#define NMAX 1000000
#define CAP 192      // rows cached in SMEM per segment (mean 122, max ~170)
#define SCAP 1024    // max segment size supported for s/node arrays

__device__ float g_qW[BMAX * DE];
__device__ int   g_hist[BMAX];
__device__ int   g_off[BMAX];
__device__ int   g_cur[BMAX];
__device__ int   g_nodes[NMAX];

// ---------------------------------------------------------------- init hist
__global__ void k_init(int B) {
    int i = blockIdx.x * blockDim.x + threadIdx.x;
    if (i < B) g_hist[i] = 0;
}

// ---------------------------------------------------------------- qW = query @ W
// 32 rows per block, 128 threads (one output dim each). W stays in L2.
__global__ void k_qw(const float* __restrict__ query, const float* __restrict__ W, int B) {
    __shared__ float qs[32][DE + 4];
    int row0 = blockIdx.x * 32;
    int t = threadIdx.x;  // 0..127
    #pragma unroll
    for (int j = 0; j < 32; j++) {
        int r = row0 + j;
        qs[j][t] = (r < B) ? query[r * DE + t] : 0.f;
    }
    __syncthreads();
    float acc[32];
    #pragma unroll
    for (int r = 0; r < 32; r++) acc[r] = 0.f;
    for (int k = 0; k < DE; k++) {
        float w = W[k * DE + t];
        #pragma unroll
        for (int r = 0; r < 32; r++) acc[r] = fmaf(qs[r][k], w, acc[r]);
    }
    #pragma unroll
    for (int r = 0; r < 32; r++) {
        int rr = row0 + r;
        if (rr < B) g_qW[rr * DE + t] = acc[r];
    }
}

// ---------------------------------------------------------------- histogram of index
__global__ void k_hist(const int* __restrict__ index, int N) {
    int i = blockIdx.x * blockDim.x + threadIdx.x;
    if (i < N) atomicAdd(&g_hist[index[i]], 1);
}

// ---------------------------------------------------------------- exclusive scan (1 block, 1024 thr, 8 bins/thr)
__global__ void k_scan(int B) {
    __shared__ int ps[1024];
    int t = threadIdx.x;
    int base = t * 8;
    int loc[8];
    int s = 0;
    #pragma unroll
    for (int j = 0; j < 8; j++) {
        int v = (base + j < B) ? g_hist[base + j] : 0;
        loc[j] = s;
        s += v;
    }
    ps[t] = s;
    __syncthreads();
    for (int o = 1; o < 1024; o <<= 1) {
        int v = (t >= o) ? ps[t - o] : 0;
        __syncthreads();
        ps[t] += v;
        __syncthreads();
    }
    int pre = (t > 0) ? ps[t - 1] : 0;
    #pragma unroll
    for (int j = 0; j < 8; j++) {
        if (base + j < B) {
            int o2 = pre + loc[j];
            g_off[base + j] = o2;
            g_cur[base + j] = o2;
        }
    }
}

// ---------------------------------------------------------------- scatter node ids into CSR
__global__ void k_scatter(const int* __restrict__ index, int N) {
    int i = blockIdx.x * blockDim.x + threadIdx.x;
    if (i < N) {
        int b = index[i];
        int p = atomicAdd(&g_cur[b], 1);
        g_nodes[p] = i;
    }
}

// ---------------------------------------------------------------- main: one block per batch row
// SMEM layout (floats): rows[CAP*DE] | sv[SCAP] | nds[SCAP](int) | qw[DE] | red[64] | part[256]
#define SMEM_FLOATS (CAP * DE + SCAP + SCAP + DE + 64 + 256)
#define SMEM_BYTES  (SMEM_FLOATS * 4)

__global__ void __launch_bounds__(256, 2) k_main(const float* __restrict__ values,
                                                 float* __restrict__ out, int N) {
    extern __shared__ float smem[];
    float* rows = smem;
    float* sv   = rows + CAP * DE;
    int*   nds  = (int*)(sv + SCAP);
    float* qw   = (float*)(nds + SCAP);
    float* red  = qw + DE;
    float* part = red + 64;

    int b = blockIdx.x;
    int tid = threadIdx.x, lane = tid & 31, wid = tid >> 5;

    int off = g_off[b];
    int cnt = g_hist[b];
    if (cnt > SCAP) cnt = SCAP;  // safety clamp (statistically unreachable)

    if (tid < DE) qw[tid] = g_qW[b * DE + tid];
    for (int i = tid; i < cnt; i += 256) nds[i] = g_nodes[off + i];
    __syncthreads();

    float4 qv = *(float4*)&qw[lane * 4];

    // Phase A: warp-per-node gather (batched x4 for MLP), cache rows in SMEM, compute scores
    for (int i = wid; i < cnt; i += 8 * 4) {
        float4 v[4];
        int nd[4];
        #pragma unroll
        for (int u = 0; u < 4; u++) {
            int ii = i + u * 8;
            if (ii < cnt) {
                nd[u] = nds[ii];
                v[u] = *(const float4*)(values + (size_t)nd[u] * DE + lane * 4);
            }
        }
        #pragma unroll
        for (int u = 0; u < 4; u++) {
            int ii = i + u * 8;
            if (ii < cnt) {
                float d = v[u].x * qv.x + v[u].y * qv.y + v[u].z * qv.z + v[u].w * qv.w;
                #pragma unroll
                for (int o = 16; o > 0; o >>= 1) d += __shfl_down_sync(0xffffffffu, d, o);
                if (ii < CAP) *(float4*)&rows[ii * DE + lane * 4] = v[u];
                if (lane == 0) sv[ii] = d * 0.08838834764831845f;  // 1/sqrt(128)
            }
        }
    }
    __syncthreads();

    // max reduce
    float m = -3.4e38f;
    for (int i = tid; i < cnt; i += 256) m = fmaxf(m, sv[i]);
    #pragma unroll
    for (int o = 16; o > 0; o >>= 1) m = fmaxf(m, __shfl_xor_sync(0xffffffffu, m, o));
    if (lane == 0) red[wid] = m;
    __syncthreads();
    if (tid == 0) {
        float mm = red[0];
        for (int w = 1; w < 8; w++) mm = fmaxf(mm, red[w]);
        red[8] = mm;
    }
    __syncthreads();
    float smax = red[8];

    // exp + sum
    float ssum = 0.f;
    for (int i = tid; i < cnt; i += 256) {
        float e = expf(sv[i] - smax);
        sv[i] = e;
        ssum += e;
    }
    #pragma unroll
    for (int o = 16; o > 0; o >>= 1) ssum += __shfl_xor_sync(0xffffffffu, ssum, o);
    if (lane == 0) red[16 + wid] = ssum;
    __syncthreads();
    if (tid == 0) {
        float s = 0.f;
        for (int w = 0; w < 8; w++) s += red[16 + w];
        red[9] = (s > 0.f) ? 1.f / s : 0.f;
    }
    __syncthreads();
    float inv = red[9];

    // Phase B: weighted pooling from SMEM cache (2 groups of 128 threads)
    int g = tid >> 7, d = tid & 127;
    float acc = 0.f;
    for (int i = g; i < cnt; i += 2) {
        float w = sv[i] * inv;
        float v = (i < CAP) ? rows[i * DE + d] : values[(size_t)nds[i] * DE + d];
        acc = fmaf(w, v, acc);
    }
    part[tid] = acc;
    __syncthreads();
    if (tid < DE) out[(size_t)b * DE + tid] = part[tid] + part[tid + DE];
}

// ---------------------------------------------------------------- launch
extern "C" void kernel_launch(void* const* d_in, const int* in_sizes, int n_in,
                              void* d_out, int out_size) {
    const float* query  = (const float*)d_in[0];
    const float* values = (const float*)d_in[1];
    const int*   index  = (const int*)d_in[2];
    const float* W      = (const float*)d_in[3];
    float* out = (float*)d_out;

    int B = in_sizes[0] / DE;   // 8192
    int N = in_sizes[2];        // 1,000,000

    cudaFuncSetAttribute(k_main, cudaFuncAttributeMaxDynamicSharedMemorySize, SMEM_BYTES);

    k_init<<<(B + 255) / 256, 256>>>(B);
    k_qw<<<(B + 31) / 32, 128>>>(query, W, B);
    k_hist<<<(N + 255) / 256, 256>>>(index, N);
    k_scan<<<1, 1024>>>(B);
    k_scatter<<<(N + 255) / 256, 256>>>(index, N);
    k_main<<<B, 256, SMEM_BYTES>>>(values, out, N);
}

// round 3
// speedup vs baseline: 1.1191x; 1.1191x over previous
#include <cuda_runtime.h>
#include <cstdint>

#define DE 128
#define BMAX 8192
#define NMAX 1000000
#define CAP 192      // rows cached in SMEM per segment (mean 122, max ~170, P(>192) ~ 1e-9)
#define SCAP 1024    // max segment size supported for s/node arrays

__device__ float g_qW[BMAX * DE];
__device__ int   g_hist[BMAX];
__device__ int   g_off[BMAX];
__device__ int   g_cur[BMAX];
__device__ int   g_nodes[NMAX];

__device__ __forceinline__ uint32_t smem_u32(const void* p) {
    uint32_t a;
    asm("{ .reg .u64 t; cvta.to.shared.u64 t, %1; cvt.u32.u64 %0, t; }" : "=r"(a) : "l"(p));
    return a;
}

// ---------------------------------------------------------------- qW = query @ W  (+ zero g_hist)
// 32 rows per block, 128 threads (one output dim each). W stays in L2.
__global__ void k_qw(const float* __restrict__ query, const float* __restrict__ W, int B) {
    // fold hist-zeroing in (runs before k_hist in stream order)
    int gidx = blockIdx.x * blockDim.x + threadIdx.x;
    if (gidx < B) g_hist[gidx] = 0;

    __shared__ float qs[32][DE + 4];
    int row0 = blockIdx.x * 32;
    int t = threadIdx.x;  // 0..127
    #pragma unroll
    for (int j = 0; j < 32; j++) {
        int r = row0 + j;
        qs[j][t] = (r < B) ? query[r * DE + t] : 0.f;
    }
    __syncthreads();
    float acc[32];
    #pragma unroll
    for (int r = 0; r < 32; r++) acc[r] = 0.f;
    for (int k = 0; k < DE; k++) {
        float w = W[k * DE + t];
        #pragma unroll
        for (int r = 0; r < 32; r++) acc[r] = fmaf(qs[r][k], w, acc[r]);
    }
    #pragma unroll
    for (int r = 0; r < 32; r++) {
        int rr = row0 + r;
        if (rr < B) g_qW[rr * DE + t] = acc[r];
    }
}

// ---------------------------------------------------------------- histogram of index (int4 loads)
__global__ void k_hist(const int* __restrict__ index, int N) {
    int i = blockIdx.x * blockDim.x + threadIdx.x;
    int i4 = i * 4;
    if (i4 + 3 < N) {
        int4 v = *(const int4*)(index + i4);
        atomicAdd(&g_hist[v.x], 1);
        atomicAdd(&g_hist[v.y], 1);
        atomicAdd(&g_hist[v.z], 1);
        atomicAdd(&g_hist[v.w], 1);
    } else {
        for (int j = i4; j < N; j++) atomicAdd(&g_hist[index[j]], 1);
    }
}

// ---------------------------------------------------------------- exclusive scan over B=8192 bins
// 256 threads, 32 bins each, int4 loads, warp-shuffle scan, single sync.
__global__ void k_scan(int B) {
    __shared__ int warp_sums[8];
    int t = threadIdx.x;          // 0..255
    int lane = t & 31, w = t >> 5;
    int base = t * 32;
    int loc[32];
    int s = 0;
    const int4* hp = (const int4*)&g_hist[base];
    #pragma unroll
    for (int j = 0; j < 8; j++) {
        int4 v = (base + j * 4 + 3 < B) ? hp[j] : make_int4(0, 0, 0, 0);
        loc[j * 4 + 0] = s; s += v.x;
        loc[j * 4 + 1] = s; s += v.y;
        loc[j * 4 + 2] = s; s += v.z;
        loc[j * 4 + 3] = s; s += v.w;
    }
    int incl = s;
    #pragma unroll
    for (int o = 1; o < 32; o <<= 1) {
        int v = __shfl_up_sync(0xffffffffu, incl, o);
        if (lane >= o) incl += v;
    }
    if (lane == 31) warp_sums[w] = incl;
    __syncthreads();
    int wpre = 0;
    #pragma unroll
    for (int k = 0; k < 8; k++) wpre += (k < w) ? warp_sums[k] : 0;
    int pre = wpre + incl - s;   // exclusive prefix for my first bin
    int4* op = (int4*)&g_off[base];
    int4* cp = (int4*)&g_cur[base];
    #pragma unroll
    for (int j = 0; j < 8; j++) {
        if (base + j * 4 + 3 < B) {
            int4 o4 = make_int4(pre + loc[j * 4 + 0], pre + loc[j * 4 + 1],
                                pre + loc[j * 4 + 2], pre + loc[j * 4 + 3]);
            op[j] = o4;
            cp[j] = o4;
        }
    }
}

// ---------------------------------------------------------------- scatter node ids into CSR
__global__ void k_scatter(const int* __restrict__ index, int N) {
    int i = blockIdx.x * blockDim.x + threadIdx.x;
    if (i < N) {
        int b = index[i];
        int p = atomicAdd(&g_cur[b], 1);
        g_nodes[p] = i;
    }
}

// ---------------------------------------------------------------- main: one block per batch row
// SMEM layout (floats): rows[CAP*DE] | sv[SCAP] | nds[SCAP](int) | qw[DE] | red[64] | part[256]
#define SMEM_FLOATS (CAP * DE + SCAP + SCAP + DE + 64 + 256)
#define SMEM_BYTES  (SMEM_FLOATS * 4)

__global__ void __launch_bounds__(256, 2) k_main(const float* __restrict__ values,
                                                 float* __restrict__ out, int N) {
    extern __shared__ float smem[];
    float* rows = smem;
    float* sv   = rows + CAP * DE;
    int*   nds  = (int*)(sv + SCAP);
    float* qw   = (float*)(nds + SCAP);
    float* red  = qw + DE;
    float* part = red + 64;

    int b = blockIdx.x;
    int tid = threadIdx.x, lane = tid & 31, wid = tid >> 5;

    int off = g_off[b];
    int cnt = g_hist[b];
    if (cnt > SCAP) cnt = SCAP;  // safety clamp (statistically unreachable)
    int capn = (cnt < CAP) ? cnt : CAP;

    if (tid < DE) qw[tid] = g_qW[b * DE + tid];
    for (int i = tid; i < cnt; i += 256) nds[i] = g_nodes[off + i];
    __syncthreads();

    float4 qv = *(float4*)&qw[lane * 4];

    // -------- Phase A1: issue ALL cached-row loads via cp.async (deep MLP pipeline)
    for (int i = wid; i < capn; i += 8) {
        int nd = nds[i];
        const float* gp = values + (size_t)nd * DE + lane * 4;
        uint32_t sa = smem_u32(&rows[i * DE + lane * 4]);
        asm volatile("cp.async.cg.shared.global [%0], [%1], 16;" :: "r"(sa), "l"(gp));
    }
    asm volatile("cp.async.commit_group;" ::: "memory");

    // overflow rows (i >= CAP): score directly from global (statistically never)
    for (int i = CAP + wid; i < cnt; i += 8) {
        int nd = nds[i];
        float4 v = *(const float4*)(values + (size_t)nd * DE + lane * 4);
        float d = v.x * qv.x + v.y * qv.y + v.z * qv.z + v.w * qv.w;
        #pragma unroll
        for (int o = 16; o > 0; o >>= 1) d += __shfl_down_sync(0xffffffffu, d, o);
        if (lane == 0) sv[i] = d * 0.08838834764831845f;
    }

    asm volatile("cp.async.wait_group 0;" ::: "memory");
    __syncthreads();

    // -------- Phase A2: scores from SMEM
    for (int i = wid; i < capn; i += 8) {
        float4 v = *(float4*)&rows[i * DE + lane * 4];
        float d = v.x * qv.x + v.y * qv.y + v.z * qv.z + v.w * qv.w;
        #pragma unroll
        for (int o = 16; o > 0; o >>= 1) d += __shfl_down_sync(0xffffffffu, d, o);
        if (lane == 0) sv[i] = d * 0.08838834764831845f;  // 1/sqrt(128)
    }
    __syncthreads();

    // -------- max reduce
    float m = -3.4e38f;
    for (int i = tid; i < cnt; i += 256) m = fmaxf(m, sv[i]);
    #pragma unroll
    for (int o = 16; o > 0; o >>= 1) m = fmaxf(m, __shfl_xor_sync(0xffffffffu, m, o));
    if (lane == 0) red[wid] = m;
    __syncthreads();
    if (tid == 0) {
        float mm = red[0];
        for (int w = 1; w < 8; w++) mm = fmaxf(mm, red[w]);
        red[8] = mm;
    }
    __syncthreads();
    float smax = red[8];

    // -------- exp + sum
    float ssum = 0.f;
    for (int i = tid; i < cnt; i += 256) {
        float e = expf(sv[i] - smax);
        sv[i] = e;
        ssum += e;
    }
    #pragma unroll
    for (int o = 16; o > 0; o >>= 1) ssum += __shfl_xor_sync(0xffffffffu, ssum, o);
    if (lane == 0) red[16 + wid] = ssum;
    __syncthreads();
    if (tid == 0) {
        float s = 0.f;
        for (int w = 0; w < 8; w++) s += red[16 + w];
        red[9] = (s > 0.f) ? 1.f / s : 0.f;
    }
    __syncthreads();
    float inv = red[9];

    // -------- Phase B: weighted pooling from SMEM cache (2 groups of 128 threads)
    int g = tid >> 7, d = tid & 127;
    float acc = 0.f;
    for (int i = g; i < cnt; i += 2) {
        float w = sv[i] * inv;
        float v = (i < CAP) ? rows[i * DE + d] : values[(size_t)nds[i] * DE + d];
        acc = fmaf(w, v, acc);
    }
    part[tid] = acc;
    __syncthreads();
    if (tid < DE) out[(size_t)b * DE + tid] = part[tid] + part[tid + DE];
}

// ---------------------------------------------------------------- launch
extern "C" void kernel_launch(void* const* d_in, const int* in_sizes, int n_in,
                              void* d_out, int out_size) {
    const float* query  = (const float*)d_in[0];
    const float* values = (const float*)d_in[1];
    const int*   index  = (const int*)d_in[2];
    const float* W      = (const float*)d_in[3];
    float* out = (float*)d_out;

    int B = in_sizes[0] / DE;   // 8192
    int N = in_sizes[2];        // 1,000,000

    cudaFuncSetAttribute(k_main, cudaFuncAttributeMaxDynamicSharedMemorySize, SMEM_BYTES);

    k_qw<<<(B + 31) / 32, 128>>>(query, W, B);
    k_hist<<<(N / 4 + 255) / 256, 256>>>(index, N);
    k_scan<<<1, 256>>>(B);
    k_scatter<<<(N + 255) / 256, 256>>>(index, N);
    k_main<<<B, 256, SMEM_BYTES>>>(values, out, N);
}